// round 8
// baseline (speedup 1.0000x reference)
#include <cuda_runtime.h>
#include <cstdint>

#define FULLMASK 0xFFFFFFFFu
typedef unsigned long long ull;

constexpr int BATCH = 256;
constexpr int HID   = 16;
constexpr int CK    = 32;    // steps per pipeline chunk
constexpr int RB    = 64;    // ring slots = 2 chunks
// 2*log2(e): folded into all weights/biases so tanh(a) = 1 - 2/(1+exp2(a'))
#define TANH_SCALE 2.885390081777927f

// ---- packed f32x2 helpers (Blackwell FFMA2 — only reachable via PTX) ----
__device__ __forceinline__ ull pack2(float lo, float hi) {
    ull r; asm("mov.b64 %0, {%1,%2};" : "=l"(r) : "f"(lo), "f"(hi)); return r;
}
__device__ __forceinline__ void unpack2(ull v, float& lo, float& hi) {
    asm("mov.b64 {%0,%1}, %2;" : "=f"(lo), "=f"(hi) : "l"(v));
}
__device__ __forceinline__ ull fma2(ull a, ull b, ull c) {
    ull d; asm("fma.rn.f32x2 %0, %1, %2, %3;" : "=l"(d) : "l"(a), "l"(b), "l"(c)); return d;
}
__device__ __forceinline__ ull add2(ull a, ull b) {
    ull d; asm("add.rn.f32x2 %0, %1, %2;" : "=l"(d) : "l"(a), "l"(b)); return d;
}

// tanh on a PRE-SCALED argument a' = 2*log2(e)*a:  tanh = 1 - 2/(1+exp2(a'))
__device__ __forceinline__ float tanh_pre(float a) {
    float e; asm("ex2.approx.f32 %0, %1;" : "=f"(e) : "f"(a));
    float r; asm("rcp.approx.f32 %0, %1;" : "=f"(r) : "f"(e + 1.0f));
    return fmaf(-2.0f, r, 1.0f);
}

// 16-float broadcast vector -> 8 packed ull via 4x LDS.128
__device__ __forceinline__ void ldp16(ull* dst, const float* bsrc) {
    const ulonglong2* p = (const ulonglong2*)bsrc;
    ulonglong2 a = p[0], b = p[1], c = p[2], d = p[3];
    dst[0] = a.x; dst[1] = a.y; dst[2] = b.x; dst[3] = b.y;
    dst[4] = c.x; dst[5] = c.y; dst[6] = d.x; dst[7] = d.y;
}

// dot16: 4 chains of depth 2 + add tree; seed goes into chain 0
__device__ __forceinline__ ull dot16(const ull* w, const ull* h, ull seed) {
    ull a0 = fma2(w[0], h[0], seed);
    ull a1 = fma2(w[2], h[2], 0ULL);
    ull a2 = fma2(w[4], h[4], 0ULL);
    ull a3 = fma2(w[6], h[6], 0ULL);
    a0 = fma2(w[1], h[1], a0);
    a1 = fma2(w[3], h[3], a1);
    a2 = fma2(w[5], h[5], a2);
    a3 = fma2(w[7], h[7], a3);
    return add2(add2(a0, a1), add2(a2, a3));
}

__global__ void __launch_bounds__(64, 1) rnn3_pipe_kernel(
    const float* __restrict__ x,        // [B, T, 1]
    const float* __restrict__ prev_h0,  // [2, 16]
    const float* __restrict__ post_h0,  // [1, 1]
    const float* __restrict__ W_ih0,    // [16, 1]
    const float* __restrict__ W_hh0,    // [16, 16]
    const float* __restrict__ b_ih0,    // [16]
    const float* __restrict__ b_hh0,    // [16]
    const float* __restrict__ W_ih1,    // [16, 16]
    const float* __restrict__ W_hh1,    // [16, 16]
    const float* __restrict__ b_ih1,    // [16]
    const float* __restrict__ b_hh1,    // [16]
    const float* __restrict__ W_ihp,    // [1, 16]
    const float* __restrict__ W_hhp,    // [1, 1]
    const float* __restrict__ b_ihp,    // [1]
    const float* __restrict__ b_hhp,    // [1]
    float* __restrict__ out,            // [B, T, 1]
    int T)
{
    const int tid  = threadIdx.x;       // 0..63
    const int wid  = tid >> 5;          // 0 = layer-0 producer, 1 = layer-1+post consumer
    const int lane = tid & 31;
    const int j    = lane & 15;         // hidden unit owned by this lane
    const int half = lane >> 4;         // 0 = batch A, 1 = batch B
    const int batch = blockIdx.x * 2 + half;

    // h0 stream ring: 64 slots x 2 batches x 16 units (8 KB). Writer (warp 0)
    // and reader (warp 1) are one chunk apart; bar.sync per chunk orders them.
    __shared__ __align__(16) float RING[RB][2][16];
    // warp-1-local h1 broadcast, 2 slots (WAR distance 2), R4-proven pattern.
    __shared__ __align__(16) float BC1[2][2][16];

    const float C = TANH_SCALE;
    const int nCk = T / CK;

    if (wid == 0) {
        // ================= producer: layer 0 =================
        ull whh0p[8];
#pragma unroll
        for (int k = 0; k < 8; k++)
            whh0p[k] = pack2(C * __ldg(&W_hh0[j * HID + 2 * k]),
                             C * __ldg(&W_hh0[j * HID + 2 * k + 1]));
        // min-max normalize folded: xn=(x+1)/2 -> wih0h*x + bh0h (pre-scaled)
        const float wih0h = 0.5f * C * __ldg(&W_ih0[j]);
        const float bh0h  = C * (__ldg(&b_ih0[j]) + __ldg(&b_hh0[j])) + wih0h;

        ull h0p[8];
#pragma unroll
        for (int k = 0; k < 8; k++)
            h0p[k] = pack2(__ldg(&prev_h0[2 * k]), __ldg(&prev_h0[2 * k + 1]));

        const float4* X = (const float4*)(x + (size_t)batch * T);
        float4 xcur = X[0], xnxt = X[1];

        for (int c = 0; c <= nCk; c++) {
            if (c < nCk) {
                const int t0 = c * CK;
#pragma unroll 1
                for (int g = 0; g < CK / 4; g++) {
#pragma unroll
                    for (int s = 0; s < 4; s++) {
                        const int t = t0 + g * 4 + s;
                        const float xt = (s == 0) ? xcur.x : (s == 1) ? xcur.y
                                       : (s == 2) ? xcur.z : xcur.w;
                        const ull xb2 = pack2(fmaf(wih0h, xt, bh0h), 0.0f);  // off-chain
                        ull ss = dot16(whh0p, h0p, xb2);
                        float lo, hi; unpack2(ss, lo, hi);
                        const float h0n = tanh_pre(lo + hi);
                        RING[t & (RB - 1)][half][j] = h0n;   // feeds warp 1 AND own bcast
                        __syncwarp();                        // drains STS -> clean LDS
                        ldp16(h0p, RING[t & (RB - 1)][half]);
                    }
                    xcur = xnxt;
                    const int tn = t0 + g * 4 + 8;
                    if (tn < T) xnxt = X[tn >> 2];
                }
            }
            asm volatile("bar.sync 0, 64;" ::: "memory");    // chunk handoff
        }
    } else {
        // ================= consumer: layer 1 + post =================
        ull wih1p[8], whh1p[8], wihpp[8];
#pragma unroll
        for (int k = 0; k < 8; k++) {
            wih1p[k] = pack2(C * __ldg(&W_ih1[j * HID + 2 * k]),
                             C * __ldg(&W_ih1[j * HID + 2 * k + 1]));
            whh1p[k] = pack2(C * __ldg(&W_hh1[j * HID + 2 * k]),
                             C * __ldg(&W_hh1[j * HID + 2 * k + 1]));
            wihpp[k] = pack2(C * __ldg(&W_ihp[2 * k]),
                             C * __ldg(&W_ihp[2 * k + 1]));
        }
        const ull  bias1_2 = pack2(C * (__ldg(&b_ih1[j]) + __ldg(&b_hh1[j])), 0.0f);
        const float whhpC  = C * __ldg(&W_hhp[0]);
        const float bpC    = C * (__ldg(&b_ihp[0]) + __ldg(&b_hhp[0]));

        ull h1p[8];
#pragma unroll
        for (int k = 0; k < 8; k++)
            h1p[k] = pack2(__ldg(&prev_h0[HID + 2 * k]), __ldg(&prev_h0[HID + 2 * k + 1]));
        float y = __ldg(&post_h0[0]);
        float* ob = out + (size_t)batch * T;

        for (int c = 0; c <= nCk; c++) {
            if (c >= 1) {
                const int t0 = (c - 1) * CK;
#pragma unroll 4
                for (int s = 0; s < CK; s++) {
                    const int t = t0 + s;

                    // h0[t] from ring (produced last pipeline iteration; slack path)
                    ull h0v[8];
                    ldp16(h0v, RING[t & (RB - 1)][half]);
                    ull uu = dot16(wih1p, h0v, bias1_2);     // u = Wih1*h0[t] + b1

                    // recurrence chain: Whh1*h1[t-1] seeded with u
                    ull tt = dot16(whh1p, h1p, uu);
                    float lo, hi; unpack2(tt, lo, hi);
                    const float h1n = tanh_pre(lo + hi);

                    // h1 broadcast (warp-local, 2 slots + syncwarp)
                    const int slot = t & 1;
                    BC1[slot][half][j] = h1n;
                    __syncwarp();
                    ldp16(h1p, BC1[slot][half]);

                    // post layer on fresh h1[t] (redundant packed dot on all lanes)
                    ull qq = dot16(wihpp, h1p, 0ULL);
                    float ql, qh; unpack2(qq, ql, qh);
                    y = tanh_pre((ql + qh) + fmaf(whhpC, y, bpC));
                    if (j == 0) ob[t] = y;
                }
            }
            asm volatile("bar.sync 0, 64;" ::: "memory");    // chunk handoff
        }
    }
}

extern "C" void kernel_launch(void* const* d_in, const int* in_sizes, int n_in,
                              void* d_out, int out_size)
{
    const float* x       = (const float*)d_in[0];
    const float* prev_h0 = (const float*)d_in[1];
    const float* post_h0 = (const float*)d_in[2];
    const float* W_ih0   = (const float*)d_in[3];
    const float* W_hh0   = (const float*)d_in[4];
    const float* b_ih0   = (const float*)d_in[5];
    const float* b_hh0   = (const float*)d_in[6];
    const float* W_ih1   = (const float*)d_in[7];
    const float* W_hh1   = (const float*)d_in[8];
    const float* b_ih1   = (const float*)d_in[9];
    const float* b_hh1   = (const float*)d_in[10];
    const float* W_ihp   = (const float*)d_in[11];
    const float* W_hhp   = (const float*)d_in[12];
    const float* b_ihp   = (const float*)d_in[13];
    const float* b_hhp   = (const float*)d_in[14];
    float* out = (float*)d_out;

    const int T = in_sizes[0] / BATCH;   // IN == 1, T = 16384 (multiple of CK)

    rnn3_pipe_kernel<<<BATCH / 2, 64>>>(
        x, prev_h0, post_h0,
        W_ih0, W_hh0, b_ih0, b_hh0,
        W_ih1, W_hh1, b_ih1, b_hh1,
        W_ihp, W_hhp, b_ihp, b_hhp,
        out, T);
}

// round 9
// speedup vs baseline: 1.2641x; 1.2641x over previous
#include <cuda_runtime.h>
#include <cstdint>

#define FULLMASK 0xFFFFFFFFu
typedef unsigned long long ull;

constexpr int BATCH = 256;
constexpr int HID   = 16;
// 2*log2(e): folded into all weights/biases so tanh(a) = 1 - 2/(1+exp2(a'))
#define TANH_SCALE 2.885390081777927f

// ---- packed f32x2 helpers (Blackwell FFMA2 — only reachable via PTX) ----
__device__ __forceinline__ ull pack2(float lo, float hi) {
    ull r; asm("mov.b64 %0, {%1,%2};" : "=l"(r) : "f"(lo), "f"(hi)); return r;
}
__device__ __forceinline__ void unpack2(ull v, float& lo, float& hi) {
    asm("mov.b64 {%0,%1}, %2;" : "=f"(lo), "=f"(hi) : "l"(v));
}
__device__ __forceinline__ ull fma2(ull a, ull b, ull c) {
    ull d; asm("fma.rn.f32x2 %0, %1, %2, %3;" : "=l"(d) : "l"(a), "l"(b), "l"(c)); return d;
}
__device__ __forceinline__ ull add2(ull a, ull b) {
    ull d; asm("add.rn.f32x2 %0, %1, %2;" : "=l"(d) : "l"(a), "l"(b)); return d;
}

// tanh on a PRE-SCALED argument a' = 2*log2(e)*a:  tanh = 1 - 2/(1+exp2(a'))
__device__ __forceinline__ float tanh_pre(float a) {
    float e; asm("ex2.approx.f32 %0, %1;" : "=f"(e) : "f"(a));
    float r; asm("rcp.approx.f32 %0, %1;" : "=f"(r) : "f"(e + 1.0f));
    return fmaf(-2.0f, r, 1.0f);
}

__global__ void __launch_bounds__(32, 1) rnn3_scan_kernel(
    const float* __restrict__ x,        // [B, T, 1]
    const float* __restrict__ prev_h0,  // [2, 16]
    const float* __restrict__ post_h0,  // [1, 1]
    const float* __restrict__ W_ih0,    // [16, 1]
    const float* __restrict__ W_hh0,    // [16, 16]
    const float* __restrict__ b_ih0,    // [16]
    const float* __restrict__ b_hh0,    // [16]
    const float* __restrict__ W_ih1,    // [16, 16]
    const float* __restrict__ W_hh1,    // [16, 16]
    const float* __restrict__ b_ih1,    // [16]
    const float* __restrict__ b_hh1,    // [16]
    const float* __restrict__ W_ihp,    // [1, 16]
    const float* __restrict__ W_hhp,    // [1, 1]
    const float* __restrict__ b_ihp,    // [1]
    const float* __restrict__ b_hhp,    // [1]
    float* __restrict__ out,            // [B, T, 1]
    int T)
{
    const int lane = threadIdx.x;       // 0..31
    const int j    = lane & 15;         // hidden unit owned by this lane
    const int half = lane >> 4;         // 0 = batch A, 1 = batch B
    const int batch = blockIdx.x * 2 + half;

    // R4-proven broadcast: two-slot smem (WAR distance 2) + __syncwarp
    // (BAR drains pending STS -> clean LDS).
    __shared__ __align__(16) float SH0[2][2][16];
    __shared__ __align__(16) float SH1[2][2][16];

    const float C = TANH_SCALE;

    // ---- register-resident, pre-scaled, pair-packed weights ----
    ull whh0p[8], wih1p[8], whh1p[8];
#pragma unroll
    for (int k = 0; k < 8; k++) {
        whh0p[k] = pack2(C * __ldg(&W_hh0[j * HID + 2 * k]), C * __ldg(&W_hh0[j * HID + 2 * k + 1]));
        wih1p[k] = pack2(C * __ldg(&W_ih1[j * HID + 2 * k]), C * __ldg(&W_ih1[j * HID + 2 * k + 1]));
        whh1p[k] = pack2(C * __ldg(&W_hh1[j * HID + 2 * k]), C * __ldg(&W_hh1[j * HID + 2 * k + 1]));
    }
    const float wih0C = C * __ldg(&W_ih0[j]);
    const float bh0C  = C * (__ldg(&b_ih0[j]) + __ldg(&b_hh0[j]));
    const float bh1C  = C * (__ldg(&b_ih1[j]) + __ldg(&b_hh1[j]));
    const float wihpC = C * __ldg(&W_ihp[j]);      // own column (butterfly post dot)
    const float whhpC = C * __ldg(&W_hhp[0]);
    const float bpC   = C * (__ldg(&b_ihp[0]) + __ldg(&b_hhp[0]));

    // min-max normalize folded: xn=(x+1)/2 -> wih0C*xn + bh0C = wih0h*x + bh0h
    const float wih0h = 0.5f * wih0C;
    const float bh0h  = bh0C + wih0h;
    const ull bias1_2 = pack2(bh1C, 0.0f);

    // ---- pipeline state entering iter i:
    //   h0p = h0[i-1], h1p = h1[i-2] (packed broadcasts),
    //   h1d1 = own-lane h1[i-2], y = y[i-3]
    ull h0p[8], h1p[8];
#pragma unroll
    for (int k = 0; k < 8; k++) {
        h0p[k] = pack2(__ldg(&prev_h0[2 * k]),       __ldg(&prev_h0[2 * k + 1]));
        h1p[k] = pack2(__ldg(&prev_h0[HID + 2 * k]), __ldg(&prev_h0[HID + 2 * k + 1]));
    }
    float h1d1 = __ldg(&prev_h0[HID + j]);
    float y    = __ldg(&post_h0[0]);

    const float* xb = x   + (size_t)batch * T;
    float*       ob = out + (size_t)batch * T;

    // ---- stage helpers ----
    auto sdot_tanh = [&](ull xb2) -> float {           // layer 0: 4 chains of depth 2, x-seed
        ull a0 = fma2(whh0p[0], h0p[0], xb2);
        ull a1 = fma2(whh0p[2], h0p[2], 0ULL);
        ull a2 = fma2(whh0p[4], h0p[4], 0ULL);
        ull a3 = fma2(whh0p[6], h0p[6], 0ULL);
        a0 = fma2(whh0p[1], h0p[1], a0);
        a1 = fma2(whh0p[3], h0p[3], a1);
        a2 = fma2(whh0p[5], h0p[5], a2);
        a3 = fma2(whh0p[7], h0p[7], a3);
        ull ss = add2(add2(a0, a1), add2(a2, a3));
        float lo, hi; unpack2(ss, lo, hi);
        return tanh_pre(lo + hi);
    };
    auto tdot_tanh = [&]() -> float {                   // layer 1: 8 chains of depth 2
        ull t0 = fma2(wih1p[0], h0p[0], bias1_2);
        ull t1 = fma2(wih1p[2], h0p[2], 0ULL);
        ull t2 = fma2(wih1p[4], h0p[4], 0ULL);
        ull t3 = fma2(wih1p[6], h0p[6], 0ULL);
        ull t4 = fma2(whh1p[0], h1p[0], 0ULL);
        ull t5 = fma2(whh1p[2], h1p[2], 0ULL);
        ull t6 = fma2(whh1p[4], h1p[4], 0ULL);
        ull t7 = fma2(whh1p[6], h1p[6], 0ULL);
        t0 = fma2(wih1p[1], h0p[1], t0);
        t1 = fma2(wih1p[3], h0p[3], t1);
        t2 = fma2(wih1p[5], h0p[5], t2);
        t3 = fma2(wih1p[7], h0p[7], t3);
        t4 = fma2(whh1p[1], h1p[1], t4);
        t5 = fma2(whh1p[3], h1p[3], t5);
        t6 = fma2(whh1p[5], h1p[5], t6);
        t7 = fma2(whh1p[7], h1p[7], t7);
        ull tt = add2(add2(add2(t0, t1), add2(t2, t3)),
                      add2(add2(t4, t5), add2(t6, t7)));
        float lo, hi; unpack2(tt, lo, hi);
        return tanh_pre(lo + hi);
    };
    auto pdot_tanh = [&]() -> float {                   // post: butterfly on own h1[i-2] (MIO)
        float pr = wihpC * h1d1;
        pr += __shfl_xor_sync(FULLMASK, pr, 1);
        pr += __shfl_xor_sync(FULLMASK, pr, 2);
        pr += __shfl_xor_sync(FULLMASK, pr, 4);
        pr += __shfl_xor_sync(FULLMASK, pr, 8);
        return tanh_pre(pr + fmaf(whhpC, y, bpC));
    };
    auto ldp = [&](ull* dst, const float* bsrc) {
        const ulonglong2* p = (const ulonglong2*)bsrc;
        ulonglong2 a = p[0], b = p[1], c = p[2], d = p[3];
        dst[0] = a.x; dst[1] = a.y; dst[2] = b.x; dst[3] = b.y;
        dst[4] = c.x; dst[5] = c.y; dst[6] = d.x; dst[7] = d.y;
    };

    float yq0 = 0.f, yq1 = 0.f, yq2 = 0.f, yq3 = 0.f;

    // ---- prologue: i = 0..3 (pipeline fill + alignment peel) ----
    {
        const float4 x03 = *(const float4*)xb;   // x[0..3]
        {   // i = 0: h0[0]
            float h0n = sdot_tanh(pack2(fmaf(wih0h, x03.x, bh0h), 0.0f));
            SH0[0][half][j] = h0n;
            __syncwarp();
            ldp(h0p, SH0[0][half]);
        }
        {   // i = 1: h0[1], h1[0]
            float h0n = sdot_tanh(pack2(fmaf(wih0h, x03.y, bh0h), 0.0f));
            float h1n = tdot_tanh();
            SH0[1][half][j] = h0n;
            SH1[1][half][j] = h1n;
            __syncwarp();
            ldp(h0p, SH0[1][half]);
            ldp(h1p, SH1[1][half]);
            h1d1 = h1n;
        }
        {   // i = 2: h0[2], h1[1], y[0]
            float h0n = sdot_tanh(pack2(fmaf(wih0h, x03.z, bh0h), 0.0f));
            float h1n = tdot_tanh();
            float yn  = pdot_tanh();
            SH0[0][half][j] = h0n;
            SH1[0][half][j] = h1n;
            __syncwarp();
            ldp(h0p, SH0[0][half]);
            ldp(h1p, SH1[0][half]);
            h1d1 = h1n;
            y = yn; yq0 = yn;
        }
        {   // i = 3: h0[3], h1[2], y[1]
            float h0n = sdot_tanh(pack2(fmaf(wih0h, x03.w, bh0h), 0.0f));
            float h1n = tdot_tanh();
            float yn  = pdot_tanh();
            SH0[1][half][j] = h0n;
            SH1[1][half][j] = h1n;
            __syncwarp();
            ldp(h0p, SH0[1][half]);
            ldp(h1p, SH1[1][half]);
            h1d1 = h1n;
            y = yn; yq1 = yn;
        }
    }

    // ---- x prefetch: aligned float4, 2-deep ----
    const float4* X = (const float4*)xb;
    float4 xcur = X[1];                       // x[4..7]
    float4 xnxt = X[2];                       // x[8..11]

    // ---- main loop: tc = 4 .. T-4 step 4; iter i = tc+s computes h0[i], h1[i-1], y[i-2] ----
    for (int tc = 4; tc < T; tc += 4) {
#pragma unroll
        for (int s = 0; s < 4; s++) {
            const int slot = s & 1;           // tc is even
            const float xt = (s == 0) ? xcur.x : (s == 1) ? xcur.y : (s == 2) ? xcur.z : xcur.w;
            const ull xb2 = pack2(fmaf(wih0h, xt, bh0h), 0.0f);   // off-chain (x prefetched)

            // Three stage dots read only OLD state -> mutually independent.
            float h0n = sdot_tanh(xb2);       // -> h0[i]
            SH0[slot][half][j] = h0n;
            float h1n = tdot_tanh();          // -> h1[i-1]
            SH1[slot][half][j] = h1n;
            float yn  = pdot_tanh();          // -> y[i-2]  (butterfly, MIO; 2-iter slack)

            __syncwarp();                     // drains STS -> clean LDS (R4 evidence)
            ldp(h0p, SH0[slot][half]);
            ldp(h1p, SH1[slot][half]);
            h1d1 = h1n;
            y = yn;

            // y[i-2] lands at queue position (s+2)&3
            if (s == 0) yq2 = yn;
            else if (s == 1) {
                yq3 = yn;
                if (j == 0) *(float4*)(ob + tc - 4) = make_float4(yq0, yq1, yq2, yq3);
            }
            else if (s == 2) yq0 = yn;
            else yq1 = yn;
        }
        xcur = xnxt;
        xnxt = (tc + 8 < T) ? X[tc / 4 + 2] : xnxt;
    }

    // ---- epilogue: i = T (h1[T-1], y[T-2]), i = T+1 (y[T-1]) ----
    {
        float h1n = tdot_tanh();   // h1[T-1]  (h0p=h0[T-1], h1p=h1[T-2])
        float yn  = pdot_tanh();   // y[T-2]   (h1d1=h1[T-2], y=y[T-3])
        h1d1 = h1n;
        y = yn; yq2 = yn;
    }
    {
        float yn = pdot_tanh();    // y[T-1]
        yq3 = yn;
        if (j == 0) *(float4*)(ob + T - 4) = make_float4(yq0, yq1, yq2, yq3);
    }
}

extern "C" void kernel_launch(void* const* d_in, const int* in_sizes, int n_in,
                              void* d_out, int out_size)
{
    const float* x       = (const float*)d_in[0];
    const float* prev_h0 = (const float*)d_in[1];
    const float* post_h0 = (const float*)d_in[2];
    const float* W_ih0   = (const float*)d_in[3];
    const float* W_hh0   = (const float*)d_in[4];
    const float* b_ih0   = (const float*)d_in[5];
    const float* b_hh0   = (const float*)d_in[6];
    const float* W_ih1   = (const float*)d_in[7];
    const float* W_hh1   = (const float*)d_in[8];
    const float* b_ih1   = (const float*)d_in[9];
    const float* b_hh1   = (const float*)d_in[10];
    const float* W_ihp   = (const float*)d_in[11];
    const float* W_hhp   = (const float*)d_in[12];
    const float* b_ihp   = (const float*)d_in[13];
    const float* b_hhp   = (const float*)d_in[14];
    float* out = (float*)d_out;

    const int T = in_sizes[0] / BATCH;   // IN == 1, T = 16384 (multiple of 4)

    rnn3_scan_kernel<<<BATCH / 2, 32>>>(
        x, prev_h0, post_h0,
        W_ih0, W_hh0, b_ih0, b_hh0,
        W_ih1, W_hh1, b_ih1, b_hh1,
        W_ihp, W_hhp, b_ihp, b_hhp,
        out, T);
}

// round 10
// speedup vs baseline: 1.3068x; 1.0338x over previous
#include <cuda_runtime.h>
#include <cstdint>

#define FULLMASK 0xFFFFFFFFu
typedef unsigned long long ull;

constexpr int BATCH = 256;
constexpr int HID   = 16;
// 2*log2(e): folded into all weights/biases so tanh(a) = 1 - 2/(1+exp2(a'))
#define TANH_SCALE 2.885390081777927f

// ---- packed f32x2 helpers (Blackwell FFMA2 — only reachable via PTX) ----
__device__ __forceinline__ ull pack2(float lo, float hi) {
    ull r; asm("mov.b64 %0, {%1,%2};" : "=l"(r) : "f"(lo), "f"(hi)); return r;
}
__device__ __forceinline__ void unpack2(ull v, float& lo, float& hi) {
    asm("mov.b64 {%0,%1}, %2;" : "=f"(lo), "=f"(hi) : "l"(v));
}
__device__ __forceinline__ ull fma2(ull a, ull b, ull c) {
    ull d; asm("fma.rn.f32x2 %0, %1, %2, %3;" : "=l"(d) : "l"(a), "l"(b), "l"(c)); return d;
}
__device__ __forceinline__ ull add2(ull a, ull b) {
    ull d; asm("add.rn.f32x2 %0, %1, %2;" : "=l"(d) : "l"(a), "l"(b)); return d;
}

// tanh on a PRE-SCALED argument a' = 2*log2(e)*a:  tanh = 1 - 2/(1+exp2(a'))
__device__ __forceinline__ float tanh_pre(float a) {
    float e; asm("ex2.approx.f32 %0, %1;" : "=f"(e) : "f"(a));
    float r; asm("rcp.approx.f32 %0, %1;" : "=f"(r) : "f"(e + 1.0f));
    return fmaf(-2.0f, r, 1.0f);
}

__global__ void __launch_bounds__(32, 1) rnn3_scan_kernel(
    const float* __restrict__ x,        // [B, T, 1]
    const float* __restrict__ prev_h0,  // [2, 16]
    const float* __restrict__ post_h0,  // [1, 1]
    const float* __restrict__ W_ih0,    // [16, 1]
    const float* __restrict__ W_hh0,    // [16, 16]
    const float* __restrict__ b_ih0,    // [16]
    const float* __restrict__ b_hh0,    // [16]
    const float* __restrict__ W_ih1,    // [16, 16]
    const float* __restrict__ W_hh1,    // [16, 16]
    const float* __restrict__ b_ih1,    // [16]
    const float* __restrict__ b_hh1,    // [16]
    const float* __restrict__ W_ihp,    // [1, 16]
    const float* __restrict__ W_hhp,    // [1, 1]
    const float* __restrict__ b_ihp,    // [1]
    const float* __restrict__ b_hhp,    // [1]
    float* __restrict__ out,            // [B, T, 1]
    int T)
{
    const int lane = threadIdx.x;       // 0..31
    const int j    = lane & 15;         // hidden unit owned by this lane
    const int half = lane >> 4;         // 0 = batch A, 1 = batch B
    const int batch = blockIdx.x * 2 + half;

    // R4-proven broadcast: two-slot smem (WAR distance 2) + __syncwarp
    // (BAR drains pending STS -> clean LDS).
    __shared__ __align__(16) float SH0[2][2][16];
    __shared__ __align__(16) float SH1[2][2][16];

    const float C = TANH_SCALE;

    // ---- register-resident, pre-scaled, pair-packed weights (R4 layout) ----
    ull whh0p[8], wih1p[8], whh1p[8], wihpp[8];
#pragma unroll
    for (int k = 0; k < 8; k++) {
        whh0p[k] = pack2(C * __ldg(&W_hh0[j * HID + 2 * k]), C * __ldg(&W_hh0[j * HID + 2 * k + 1]));
        wih1p[k] = pack2(C * __ldg(&W_ih1[j * HID + 2 * k]), C * __ldg(&W_ih1[j * HID + 2 * k + 1]));
        whh1p[k] = pack2(C * __ldg(&W_hh1[j * HID + 2 * k]), C * __ldg(&W_hh1[j * HID + 2 * k + 1]));
        wihpp[k] = pack2(C * __ldg(&W_ihp[2 * k]),           C * __ldg(&W_ihp[2 * k + 1]));
    }
    const float wih0C = C * __ldg(&W_ih0[j]);
    const float bh0C  = C * (__ldg(&b_ih0[j]) + __ldg(&b_hh0[j]));
    const float bh1C  = C * (__ldg(&b_ih1[j]) + __ldg(&b_hh1[j]));
    const float whhpC = C * __ldg(&W_hhp[0]);
    const float bpC   = C * (__ldg(&b_ihp[0]) + __ldg(&b_hhp[0]));

    // min-max normalize folded: xn=(x+1)/2 -> wih0C*xn + bh0C = wih0h*x + bh0h
    const float wih0h = 0.5f * wih0C;
    const float bh0h  = bh0C + wih0h;
    const ull bias0_2 = pack2(bh0h, 0.0f);
    const ull bias1_2 = pack2(bh1C, 0.0f);

    // ---- DOUBLE-BUFFERED pipeline state (sets alternate by iteration parity).
    // Entering iter i with p = i&1:  h0p[p] = h0[i-1], h1p[p] = h1[i-2], y = y[i-3].
    // Iter i loads fresh broadcasts into set q = 1-p; pdot reads set p -> the
    // LDS can issue BEFORE pdot and its latency hides under remaining issue.
    ull h0p[2][8], h1p[2][8];
#pragma unroll
    for (int k = 0; k < 8; k++) {
        h0p[0][k] = h0p[1][k] = pack2(__ldg(&prev_h0[2 * k]),       __ldg(&prev_h0[2 * k + 1]));
        h1p[0][k] = h1p[1][k] = pack2(__ldg(&prev_h0[HID + 2 * k]), __ldg(&prev_h0[HID + 2 * k + 1]));
    }
    float y = __ldg(&post_h0[0]);

    const float* xb = x   + (size_t)batch * T;
    float*       ob = out + (size_t)batch * T;

    // ---- stage helpers (R4's exact dot structure) ----
    auto sdot_tanh = [&](const ull* h0v, float xt) -> float {   // layer 0
        ull s0 = fma2(whh0p[0], h0v[0], bias0_2);
        ull s1 = fma2(whh0p[4], h0v[4], 0ULL);
#pragma unroll
        for (int k = 1; k < 4; k++) {
            s0 = fma2(whh0p[k],     h0v[k],     s0);
            s1 = fma2(whh0p[4 + k], h0v[4 + k], s1);
        }
        ull ss = add2(s0, s1);
        float lo, hi; unpack2(ss, lo, hi);
        return tanh_pre(fmaf(wih0h, xt, lo + hi));
    };
    auto tdot_tanh = [&](const ull* h0v, const ull* h1v) -> float {  // layer 1
        ull t0 = fma2(wih1p[0], h0v[0], bias1_2);
        ull t1 = fma2(wih1p[4], h0v[4], 0ULL);
        ull t2 = fma2(whh1p[0], h1v[0], 0ULL);
        ull t3 = fma2(whh1p[4], h1v[4], 0ULL);
#pragma unroll
        for (int k = 1; k < 4; k++) {
            t0 = fma2(wih1p[k],     h0v[k],     t0);
            t1 = fma2(wih1p[4 + k], h0v[4 + k], t1);
            t2 = fma2(whh1p[k],     h1v[k],     t2);
            t3 = fma2(whh1p[4 + k], h1v[4 + k], t3);
        }
        ull tt = add2(add2(t0, t1), add2(t2, t3));
        float lo, hi; unpack2(tt, lo, hi);
        return tanh_pre(lo + hi);
    };
    auto pdot_tanh = [&](const ull* h1v) -> float {   // post: packed redundant dot (R4)
        ull q0 = fma2(wihpp[0], h1v[0], 0ULL);
        ull q1 = fma2(wihpp[4], h1v[4], 0ULL);
#pragma unroll
        for (int k = 1; k < 4; k++) {
            q0 = fma2(wihpp[k],     h1v[k],     q0);
            q1 = fma2(wihpp[4 + k], h1v[4 + k], q1);
        }
        ull qq = add2(q0, q1);
        float lo, hi; unpack2(qq, lo, hi);
        return tanh_pre((lo + hi) + fmaf(whhpC, y, bpC));
    };
    auto ldp = [&](ull* dst, const float* bsrc) {
        const ulonglong2* p = (const ulonglong2*)bsrc;
        ulonglong2 a = p[0], b = p[1], c = p[2], d = p[3];
        dst[0] = a.x; dst[1] = a.y; dst[2] = b.x; dst[3] = b.y;
        dst[4] = c.x; dst[5] = c.y; dst[6] = d.x; dst[7] = d.y;
    };

    float yq0 = 0.f, yq1 = 0.f, yq2 = 0.f, yq3 = 0.f;

    // ---- prologue: i = 0..3 (pipeline fill + alignment peel) ----
    {
        const float4 x03 = *(const float4*)xb;   // x[0..3]
        {   // i = 0 (p=0): h0[0] -> set 1
            float h0n = sdot_tanh(h0p[0], x03.x);
            SH0[0][half][j] = h0n;
            __syncwarp();
            ldp(h0p[1], SH0[0][half]);
        }
        {   // i = 1 (p=1): h0[1], h1[0] -> set 0
            float h0n = sdot_tanh(h0p[1], x03.y);
            float h1n = tdot_tanh(h0p[1], h1p[1]);
            SH0[1][half][j] = h0n;
            SH1[1][half][j] = h1n;
            __syncwarp();
            ldp(h0p[0], SH0[1][half]);
            ldp(h1p[0], SH1[1][half]);
        }
        {   // i = 2 (p=0): h0[2], h1[1] -> set 1;  y[0]
            float h0n = sdot_tanh(h0p[0], x03.z);
            float h1n = tdot_tanh(h0p[0], h1p[0]);
            SH0[0][half][j] = h0n;
            SH1[0][half][j] = h1n;
            __syncwarp();
            ldp(h0p[1], SH0[0][half]);
            ldp(h1p[1], SH1[0][half]);
            float yn = pdot_tanh(h1p[0]);   // uses h1[0], y[-1]
            y = yn; yq0 = yn;
        }
        {   // i = 3 (p=1): h0[3], h1[2] -> set 0;  y[1]
            float h0n = sdot_tanh(h0p[1], x03.w);
            float h1n = tdot_tanh(h0p[1], h1p[1]);
            SH0[1][half][j] = h0n;
            SH1[1][half][j] = h1n;
            __syncwarp();
            ldp(h0p[0], SH0[1][half]);
            ldp(h1p[0], SH1[1][half]);
            float yn = pdot_tanh(h1p[1]);   // uses h1[1], y[0]
            y = yn; yq1 = yn;
        }
    }

    // ---- x prefetch: aligned float4, 2-deep ----
    const float4* X = (const float4*)xb;
    float4 xcur = X[1];                       // x[4..7]
    float4 xnxt = X[2];                       // x[8..11]

    // ---- main loop: tc = 4 .. T-4 step 4; iter i = tc+s computes h0[i], h1[i-1], y[i-2] ----
    for (int tc = 4; tc < T; tc += 4) {
#pragma unroll
        for (int s = 0; s < 4; s++) {
            const int p = s & 1;              // tc even -> parity of i
            const int q = p ^ 1;
            const float xt = (s == 0) ? xcur.x : (s == 1) ? xcur.y : (s == 2) ? xcur.z : xcur.w;

            float h0n = sdot_tanh(h0p[p], xt);        // -> h0[i]
            SH0[p][half][j] = h0n;
            float h1n = tdot_tanh(h0p[p], h1p[p]);    // -> h1[i-1]
            SH1[p][half][j] = h1n;

            __syncwarp();                             // drains STS -> clean LDS
            ldp(h0p[q], SH0[p][half]);                // fresh broadcasts into set q;
            ldp(h1p[q], SH1[p][half]);                // latency hides under pdot below

            float yn = pdot_tanh(h1p[p]);             // -> y[i-2] (old set p)
            y = yn;

            // y[i-2] lands at queue position (s+2)&3
            if (s == 0) yq2 = yn;
            else if (s == 1) {
                yq3 = yn;
                if (j == 0) *(float4*)(ob + tc - 4) = make_float4(yq0, yq1, yq2, yq3);
            }
            else if (s == 2) yq0 = yn;
            else yq1 = yn;
        }
        xcur = xnxt;
        xnxt = (tc + 8 < T) ? X[tc / 4 + 2] : xnxt;
    }

    // ---- epilogue: i = T (h1[T-1], y[T-2]), i = T+1 (y[T-1]) ----
    {   // i = T (p=0): set0 = { h0[T-1], h1[T-2] }
        float h1n = tdot_tanh(h0p[0], h1p[0]);   // h1[T-1]
        SH1[0][half][j] = h1n;
        __syncwarp();
        ldp(h1p[1], SH1[0][half]);
        float yn = pdot_tanh(h1p[0]);            // y[T-2] (h1[T-2], y[T-3])
        y = yn; yq2 = yn;
    }
    {   // i = T+1 (p=1): y[T-1]
        float yn = pdot_tanh(h1p[1]);            // (h1[T-1], y[T-2])
        yq3 = yn;
        if (j == 0) *(float4*)(ob + T - 4) = make_float4(yq0, yq1, yq2, yq3);
    }
}

extern "C" void kernel_launch(void* const* d_in, const int* in_sizes, int n_in,
                              void* d_out, int out_size)
{
    const float* x       = (const float*)d_in[0];
    const float* prev_h0 = (const float*)d_in[1];
    const float* post_h0 = (const float*)d_in[2];
    const float* W_ih0   = (const float*)d_in[3];
    const float* W_hh0   = (const float*)d_in[4];
    const float* b_ih0   = (const float*)d_in[5];
    const float* b_hh0   = (const float*)d_in[6];
    const float* W_ih1   = (const float*)d_in[7];
    const float* W_hh1   = (const float*)d_in[8];
    const float* b_ih1   = (const float*)d_in[9];
    const float* b_hh1   = (const float*)d_in[10];
    const float* W_ihp   = (const float*)d_in[11];
    const float* W_hhp   = (const float*)d_in[12];
    const float* b_ihp   = (const float*)d_in[13];
    const float* b_hhp   = (const float*)d_in[14];
    float* out = (float*)d_out;

    const int T = in_sizes[0] / BATCH;   // IN == 1, T = 16384 (multiple of 4)

    rnn3_scan_kernel<<<BATCH / 2, 32>>>(
        x, prev_h0, post_h0,
        W_ih0, W_hh0, b_ih0, b_hh0,
        W_ih1, W_hh1, b_ih1, b_hh1,
        W_ihp, W_hhp, b_ihp, b_hhp,
        out, T);
}

// round 11
// speedup vs baseline: 1.9377x; 1.4828x over previous
#include <cuda_runtime.h>
#include <cstdint>

#define FULLMASK 0xFFFFFFFFu
typedef unsigned long long ull;

constexpr int BATCH = 256;
constexpr int HID   = 16;

// ---- packed f32x2 helpers (Blackwell FFMA2 — only reachable via PTX) ----
__device__ __forceinline__ ull pack2(float lo, float hi) {
    ull r; asm("mov.b64 %0, {%1,%2};" : "=l"(r) : "f"(lo), "f"(hi)); return r;
}
__device__ __forceinline__ void unpack2(ull v, float& lo, float& hi) {
    asm("mov.b64 {%0,%1}, %2;" : "=f"(lo), "=f"(hi) : "l"(v));
}
__device__ __forceinline__ ull fma2(ull a, ull b, ull c) {
    ull d; asm("fma.rn.f32x2 %0, %1, %2, %3;" : "=l"(d) : "l"(a), "l"(b), "l"(c)); return d;
}
__device__ __forceinline__ ull add2(ull a, ull b) {
    ull d; asm("add.rn.f32x2 %0, %1, %2;" : "=l"(d) : "l"(a), "l"(b)); return d;
}

// Single-instruction tanh: MUFU.TANH (sm_75+). ~16 cyc vs ~40 for the
// ex2+rcp construction, and removes 2 fma-pipe ops per call.
// Max abs err ~5e-4 worst-case; output rel_err budget is 1e-3 with the
// exact version measuring 5.2e-7 -> ample margin.
__device__ __forceinline__ float tanh_fast(float a) {
    float r; asm("tanh.approx.f32 %0, %1;" : "=f"(r) : "f"(a));
    return r;
}

__global__ void __launch_bounds__(32, 1) rnn3_scan_kernel(
    const float* __restrict__ x,        // [B, T, 1]
    const float* __restrict__ prev_h0,  // [2, 16]
    const float* __restrict__ post_h0,  // [1, 1]
    const float* __restrict__ W_ih0,    // [16, 1]
    const float* __restrict__ W_hh0,    // [16, 16]
    const float* __restrict__ b_ih0,    // [16]
    const float* __restrict__ b_hh0,    // [16]
    const float* __restrict__ W_ih1,    // [16, 16]
    const float* __restrict__ W_hh1,    // [16, 16]
    const float* __restrict__ b_ih1,    // [16]
    const float* __restrict__ b_hh1,    // [16]
    const float* __restrict__ W_ihp,    // [1, 16]
    const float* __restrict__ W_hhp,    // [1, 1]
    const float* __restrict__ b_ihp,    // [1]
    const float* __restrict__ b_hhp,    // [1]
    float* __restrict__ out,            // [B, T, 1]
    int T)
{
    const int lane = threadIdx.x;       // 0..31
    const int j    = lane & 15;         // hidden unit owned by this lane
    const int half = lane >> 4;         // 0 = batch A, 1 = batch B
    const int batch = blockIdx.x * 2 + half;

    // R4-proven broadcast: two-slot smem (WAR distance 2) + __syncwarp
    // (BAR drains pending STS -> clean LDS). pdot sits between the STS and
    // the BAR so the drain overlaps its issue (R10 lesson).
    __shared__ __align__(16) float SH0[2][2][16];
    __shared__ __align__(16) float SH1[2][2][16];

    // ---- register-resident, pair-packed weights (UNscaled — MUFU tanh) ----
    ull whh0p[8], wih1p[8], whh1p[8], wihpp[8];
#pragma unroll
    for (int k = 0; k < 8; k++) {
        whh0p[k] = pack2(__ldg(&W_hh0[j * HID + 2 * k]), __ldg(&W_hh0[j * HID + 2 * k + 1]));
        wih1p[k] = pack2(__ldg(&W_ih1[j * HID + 2 * k]), __ldg(&W_ih1[j * HID + 2 * k + 1]));
        whh1p[k] = pack2(__ldg(&W_hh1[j * HID + 2 * k]), __ldg(&W_hh1[j * HID + 2 * k + 1]));
        wihpp[k] = pack2(__ldg(&W_ihp[2 * k]),           __ldg(&W_ihp[2 * k + 1]));
    }
    const float wih0 = __ldg(&W_ih0[j]);
    const float bh0  = __ldg(&b_ih0[j]) + __ldg(&b_hh0[j]);
    const float bh1  = __ldg(&b_ih1[j]) + __ldg(&b_hh1[j]);
    const float whhp = __ldg(&W_hhp[0]);
    const float bp   = __ldg(&b_ihp[0]) + __ldg(&b_hhp[0]);

    // min-max normalize folded: xn=(x+1)/2 -> wih0*xn + bh0 = wih0h*x + bh0h
    const float wih0h = 0.5f * wih0;
    const float bh0h  = bh0 + wih0h;
    const ull bias0_2 = pack2(bh0h, 0.0f);
    const ull bias1_2 = pack2(bh1, 0.0f);

    // ---- pipeline state: entering iter i, h0p = h0[i-1], h1p = h1[i-2], y = y[i-3]
    ull h0p[8], h1p[8];
#pragma unroll
    for (int k = 0; k < 8; k++) {
        h0p[k] = pack2(__ldg(&prev_h0[2 * k]),       __ldg(&prev_h0[2 * k + 1]));
        h1p[k] = pack2(__ldg(&prev_h0[HID + 2 * k]), __ldg(&prev_h0[HID + 2 * k + 1]));
    }
    float y = __ldg(&post_h0[0]);

    const float* xb = x   + (size_t)batch * T;
    float*       ob = out + (size_t)batch * T;

    // ---- stage helpers (R4's exact dot structure, MUFU tanh) ----
    auto sdot_tanh = [&](float xt) -> float {          // layer 0: reads h0p
        ull s0 = fma2(whh0p[0], h0p[0], bias0_2);
        ull s1 = fma2(whh0p[4], h0p[4], 0ULL);
#pragma unroll
        for (int k = 1; k < 4; k++) {
            s0 = fma2(whh0p[k],     h0p[k],     s0);
            s1 = fma2(whh0p[4 + k], h0p[4 + k], s1);
        }
        ull ss = add2(s0, s1);
        float lo, hi; unpack2(ss, lo, hi);
        return tanh_fast(fmaf(wih0h, xt, lo + hi));    // x-term off the LDS->fma chain
    };
    auto tdot_tanh = [&]() -> float {                   // layer 1: reads h0p, h1p
        ull t0 = fma2(wih1p[0], h0p[0], bias1_2);
        ull t1 = fma2(wih1p[4], h0p[4], 0ULL);
        ull t2 = fma2(whh1p[0], h1p[0], 0ULL);
        ull t3 = fma2(whh1p[4], h1p[4], 0ULL);
#pragma unroll
        for (int k = 1; k < 4; k++) {
            t0 = fma2(wih1p[k],     h0p[k],     t0);
            t1 = fma2(wih1p[4 + k], h0p[4 + k], t1);
            t2 = fma2(whh1p[k],     h1p[k],     t2);
            t3 = fma2(whh1p[4 + k], h1p[4 + k], t3);
        }
        ull tt = add2(add2(t0, t1), add2(t2, t3));
        float lo, hi; unpack2(tt, lo, hi);
        return tanh_fast(lo + hi);
    };
    auto pdot_tanh = [&]() -> float {                   // post: packed redundant dot on h1p
        ull q0 = fma2(wihpp[0], h1p[0], 0ULL);
        ull q1 = fma2(wihpp[4], h1p[4], 0ULL);
#pragma unroll
        for (int k = 1; k < 4; k++) {
            q0 = fma2(wihpp[k],     h1p[k],     q0);
            q1 = fma2(wihpp[4 + k], h1p[4 + k], q1);
        }
        ull qq = add2(q0, q1);
        float lo, hi; unpack2(qq, lo, hi);
        return tanh_fast((lo + hi) + fmaf(whhp, y, bp));
    };
    auto ldp = [&](ull* dst, const float* bsrc) {
        const ulonglong2* p = (const ulonglong2*)bsrc;
        ulonglong2 a = p[0], b = p[1], c = p[2], d = p[3];
        dst[0] = a.x; dst[1] = a.y; dst[2] = b.x; dst[3] = b.y;
        dst[4] = c.x; dst[5] = c.y; dst[6] = d.x; dst[7] = d.y;
    };

    float yq0 = 0.f, yq1 = 0.f, yq2 = 0.f, yq3 = 0.f;

    // ---- prologue: i = 0..3 (pipeline fill + alignment peel) ----
    {
        const float4 x03 = *(const float4*)xb;   // x[0..3]
        {   // i = 0: h0[0]
            float h0n = sdot_tanh(x03.x);
            SH0[0][half][j] = h0n;
            __syncwarp();
            ldp(h0p, SH0[0][half]);
        }
        {   // i = 1: h0[1], h1[0]
            float h0n = sdot_tanh(x03.y);
            float h1n = tdot_tanh();
            SH0[1][half][j] = h0n;
            SH1[1][half][j] = h1n;
            __syncwarp();
            ldp(h0p, SH0[1][half]);
            ldp(h1p, SH1[1][half]);
        }
        {   // i = 2: h0[2], h1[1], y[0]
            float h0n = sdot_tanh(x03.z);
            float h1n = tdot_tanh();
            float yn  = pdot_tanh();
            SH0[0][half][j] = h0n;
            SH1[0][half][j] = h1n;
            __syncwarp();
            ldp(h0p, SH0[0][half]);
            ldp(h1p, SH1[0][half]);
            y = yn; yq0 = yn;
        }
        {   // i = 3: h0[3], h1[2], y[1]
            float h0n = sdot_tanh(x03.w);
            float h1n = tdot_tanh();
            float yn  = pdot_tanh();
            SH0[1][half][j] = h0n;
            SH1[1][half][j] = h1n;
            __syncwarp();
            ldp(h0p, SH0[1][half]);
            ldp(h1p, SH1[1][half]);
            y = yn; yq1 = yn;
        }
    }

    // ---- x prefetch: aligned float4, 2-deep ----
    const float4* X = (const float4*)xb;
    float4 xcur = X[1];                       // x[4..7]
    float4 xnxt = X[2];                       // x[8..11]

    // ---- main loop: tc = 4 .. T-4 step 4; iter i = tc+s computes h0[i], h1[i-1], y[i-2] ----
    for (int tc = 4; tc < T; tc += 4) {
#pragma unroll
        for (int s = 0; s < 4; s++) {
            const int slot = s & 1;           // tc is even
            const float xt = (s == 0) ? xcur.x : (s == 1) ? xcur.y : (s == 2) ? xcur.z : xcur.w;

            // All three stage dots read only OLD state -> mutually independent.
            float h0n = sdot_tanh(xt);        // -> h0[i]
            SH0[slot][half][j] = h0n;         // store as soon as available
            float h1n = tdot_tanh();          // -> h1[i-1]
            SH1[slot][half][j] = h1n;
            float yn  = pdot_tanh();          // -> y[i-2]  (issues while STS drains)

            __syncwarp();                     // drains STS -> clean LDS (R4 evidence)
            ldp(h0p, SH0[slot][half]);
            ldp(h1p, SH1[slot][half]);
            y = yn;

            // y[i-2] lands at queue position (s+2)&3
            if (s == 0) yq2 = yn;
            else if (s == 1) {
                yq3 = yn;
                if (j == 0) *(float4*)(ob + tc - 4) = make_float4(yq0, yq1, yq2, yq3);
            }
            else if (s == 2) yq0 = yn;
            else yq1 = yn;
        }
        xcur = xnxt;
        xnxt = (tc + 8 < T) ? X[tc / 4 + 2] : xnxt;
    }

    // ---- epilogue: i = T (h1[T-1], y[T-2]), i = T+1 (y[T-1]) ----
    {
        float h1n = tdot_tanh();   // h1[T-1]  (h0p=h0[T-1], h1p=h1[T-2])
        float yn  = pdot_tanh();   // y[T-2]
        SH1[0][half][j] = h1n;
        __syncwarp();
        ldp(h1p, SH1[0][half]);
        y = yn; yq2 = yn;
    }
    {
        float yn = pdot_tanh();    // y[T-1]
        yq3 = yn;
        if (j == 0) *(float4*)(ob + T - 4) = make_float4(yq0, yq1, yq2, yq3);
    }
}

extern "C" void kernel_launch(void* const* d_in, const int* in_sizes, int n_in,
                              void* d_out, int out_size)
{
    const float* x       = (const float*)d_in[0];
    const float* prev_h0 = (const float*)d_in[1];
    const float* post_h0 = (const float*)d_in[2];
    const float* W_ih0   = (const float*)d_in[3];
    const float* W_hh0   = (const float*)d_in[4];
    const float* b_ih0   = (const float*)d_in[5];
    const float* b_hh0   = (const float*)d_in[6];
    const float* W_ih1   = (const float*)d_in[7];
    const float* W_hh1   = (const float*)d_in[8];
    const float* b_ih1   = (const float*)d_in[9];
    const float* b_hh1   = (const float*)d_in[10];
    const float* W_ihp   = (const float*)d_in[11];
    const float* W_hhp   = (const float*)d_in[12];
    const float* b_ihp   = (const float*)d_in[13];
    const float* b_hhp   = (const float*)d_in[14];
    float* out = (float*)d_out;

    const int T = in_sizes[0] / BATCH;   // IN == 1, T = 16384 (multiple of 4)

    rnn3_scan_kernel<<<BATCH / 2, 32>>>(
        x, prev_h0, post_h0,
        W_ih0, W_hh0, b_ih0, b_hh0,
        W_ih1, W_hh1, b_ih1, b_hh1,
        W_ihp, W_hhp, b_ihp, b_hhp,
        out, T);
}

// round 12
// speedup vs baseline: 1.9625x; 1.0128x over previous
#include <cuda_runtime.h>
#include <cstdint>

#define FULLMASK 0xFFFFFFFFu
typedef unsigned long long ull;

constexpr int BATCH = 256;
constexpr int HID   = 16;

// ---- packed f32x2 helpers (Blackwell FFMA2 — only reachable via PTX) ----
__device__ __forceinline__ ull pack2(float lo, float hi) {
    ull r; asm("mov.b64 %0, {%1,%2};" : "=l"(r) : "f"(lo), "f"(hi)); return r;
}
__device__ __forceinline__ void unpack2(ull v, float& lo, float& hi) {
    asm("mov.b64 {%0,%1}, %2;" : "=f"(lo), "=f"(hi) : "l"(v));
}
__device__ __forceinline__ ull fma2(ull a, ull b, ull c) {
    ull d; asm("fma.rn.f32x2 %0, %1, %2, %3;" : "=l"(d) : "l"(a), "l"(b), "l"(c)); return d;
}
__device__ __forceinline__ ull add2(ull a, ull b) {
    ull d; asm("add.rn.f32x2 %0, %1, %2;" : "=l"(d) : "l"(a), "l"(b)); return d;
}

// Single-instruction tanh: MUFU.TANH (sm_75+), ~16 cyc. rel_err measured
// 1.04e-5 with this (R11) against 1e-3 budget.
__device__ __forceinline__ float tanh_fast(float a) {
    float r; asm("tanh.approx.f32 %0, %1;" : "=f"(r) : "f"(a));
    return r;
}

__global__ void __launch_bounds__(32, 1) rnn3_scan_kernel(
    const float* __restrict__ x,        // [B, T, 1]
    const float* __restrict__ prev_h0,  // [2, 16]
    const float* __restrict__ post_h0,  // [1, 1]
    const float* __restrict__ W_ih0,    // [16, 1]
    const float* __restrict__ W_hh0,    // [16, 16]
    const float* __restrict__ b_ih0,    // [16]
    const float* __restrict__ b_hh0,    // [16]
    const float* __restrict__ W_ih1,    // [16, 16]
    const float* __restrict__ W_hh1,    // [16, 16]
    const float* __restrict__ b_ih1,    // [16]
    const float* __restrict__ b_hh1,    // [16]
    const float* __restrict__ W_ihp,    // [1, 16]
    const float* __restrict__ W_hhp,    // [1, 1]
    const float* __restrict__ b_ihp,    // [1]
    const float* __restrict__ b_hhp,    // [1]
    float* __restrict__ out,            // [B, T, 1]
    int T)
{
    const int lane = threadIdx.x;       // 0..31
    const int j    = lane & 15;         // hidden unit owned by this lane
    const int half = lane >> 4;         // 0 = batch A, 1 = batch B
    const int batch = blockIdx.x * 2 + half;

    // Two-slot smem broadcast (WAR distance 2). NO __syncwarp in the hot
    // loop this round: the same-iteration STS->LDS RAW targets the same
    // compile-time address (loop unrolled), so the dependency is preserved
    // and the LSU enforces the drain; the BAR only added ~25 cyc + a
    // scheduling wall. (R5's no-BAR regression was the SINGLE-slot WAR,
    // distance 1 -- not the missing BAR.)
    __shared__ __align__(16) float SH0[2][2][16];
    __shared__ __align__(16) float SH1[2][2][16];

    // ---- register-resident, pair-packed weights ----
    ull whh0p[8], wih1p[8], whh1p[8], wihpp[8];
#pragma unroll
    for (int k = 0; k < 8; k++) {
        whh0p[k] = pack2(__ldg(&W_hh0[j * HID + 2 * k]), __ldg(&W_hh0[j * HID + 2 * k + 1]));
        wih1p[k] = pack2(__ldg(&W_ih1[j * HID + 2 * k]), __ldg(&W_ih1[j * HID + 2 * k + 1]));
        whh1p[k] = pack2(__ldg(&W_hh1[j * HID + 2 * k]), __ldg(&W_hh1[j * HID + 2 * k + 1]));
        wihpp[k] = pack2(__ldg(&W_ihp[2 * k]),           __ldg(&W_ihp[2 * k + 1]));
    }
    const float wih0 = __ldg(&W_ih0[j]);
    const float bh0  = __ldg(&b_ih0[j]) + __ldg(&b_hh0[j]);
    const float bh1  = __ldg(&b_ih1[j]) + __ldg(&b_hh1[j]);
    const float whhp = __ldg(&W_hhp[0]);
    const float bp   = __ldg(&b_ihp[0]) + __ldg(&b_hhp[0]);

    // min-max normalize folded: xn=(x+1)/2 -> wih0*xn + bh0 = wih0h*x + bh0h
    const float wih0h = 0.5f * wih0;
    const float bh0h  = bh0 + wih0h;
    const ull bias0_2 = pack2(bh0h, 0.0f);
    const ull bias1_2 = pack2(bh1, 0.0f);

    // ---- pipeline state: entering iter i, h0p = h0[i-1], h1p = h1[i-2], y = y[i-3]
    ull h0p[8], h1p[8];
#pragma unroll
    for (int k = 0; k < 8; k++) {
        h0p[k] = pack2(__ldg(&prev_h0[2 * k]),       __ldg(&prev_h0[2 * k + 1]));
        h1p[k] = pack2(__ldg(&prev_h0[HID + 2 * k]), __ldg(&prev_h0[HID + 2 * k + 1]));
    }
    float y = __ldg(&post_h0[0]);

    const float* xb = x   + (size_t)batch * T;
    float*       ob = out + (size_t)batch * T;

    // ---- stage helpers (R11's exact dot structure) ----
    auto sdot_tanh = [&](float xt) -> float {          // layer 0: reads h0p
        ull s0 = fma2(whh0p[0], h0p[0], bias0_2);
        ull s1 = fma2(whh0p[4], h0p[4], 0ULL);
#pragma unroll
        for (int k = 1; k < 4; k++) {
            s0 = fma2(whh0p[k],     h0p[k],     s0);
            s1 = fma2(whh0p[4 + k], h0p[4 + k], s1);
        }
        ull ss = add2(s0, s1);
        float lo, hi; unpack2(ss, lo, hi);
        return tanh_fast(fmaf(wih0h, xt, lo + hi));
    };
    auto tdot_tanh = [&]() -> float {                   // layer 1: reads h0p, h1p
        ull t0 = fma2(wih1p[0], h0p[0], bias1_2);
        ull t1 = fma2(wih1p[4], h0p[4], 0ULL);
        ull t2 = fma2(whh1p[0], h1p[0], 0ULL);
        ull t3 = fma2(whh1p[4], h1p[4], 0ULL);
#pragma unroll
        for (int k = 1; k < 4; k++) {
            t0 = fma2(wih1p[k],     h0p[k],     t0);
            t1 = fma2(wih1p[4 + k], h0p[4 + k], t1);
            t2 = fma2(whh1p[k],     h1p[k],     t2);
            t3 = fma2(whh1p[4 + k], h1p[4 + k], t3);
        }
        ull tt = add2(add2(t0, t1), add2(t2, t3));
        float lo, hi; unpack2(tt, lo, hi);
        return tanh_fast(lo + hi);
    };
    auto pdot_tanh = [&]() -> float {                   // post: packed redundant dot on h1p
        ull q0 = fma2(wihpp[0], h1p[0], 0ULL);
        ull q1 = fma2(wihpp[4], h1p[4], 0ULL);
#pragma unroll
        for (int k = 1; k < 4; k++) {
            q0 = fma2(wihpp[k],     h1p[k],     q0);
            q1 = fma2(wihpp[4 + k], h1p[4 + k], q1);
        }
        ull qq = add2(q0, q1);
        float lo, hi; unpack2(qq, lo, hi);
        return tanh_fast((lo + hi) + fmaf(whhp, y, bp));
    };
    auto ldp = [&](ull* dst, const float* bsrc) {
        const ulonglong2* p = (const ulonglong2*)bsrc;
        ulonglong2 a = p[0], b = p[1], c = p[2], d = p[3];
        dst[0] = a.x; dst[1] = a.y; dst[2] = b.x; dst[3] = b.y;
        dst[4] = c.x; dst[5] = c.y; dst[6] = d.x; dst[7] = d.y;
    };

    float yq0 = 0.f, yq1 = 0.f, yq2 = 0.f, yq3 = 0.f;

    // ---- prologue: i = 0..3 (pipeline fill + alignment peel), with barrier ----
    {
        const float4 x03 = *(const float4*)xb;   // x[0..3]
        {   // i = 0: h0[0]
            float h0n = sdot_tanh(x03.x);
            SH0[0][half][j] = h0n;
            __syncwarp();
            ldp(h0p, SH0[0][half]);
        }
        {   // i = 1: h0[1], h1[0]
            float h0n = sdot_tanh(x03.y);
            float h1n = tdot_tanh();
            SH0[1][half][j] = h0n;
            SH1[1][half][j] = h1n;
            __syncwarp();
            ldp(h0p, SH0[1][half]);
            ldp(h1p, SH1[1][half]);
        }
        {   // i = 2: h0[2], h1[1], y[0]
            float h0n = sdot_tanh(x03.z);
            float h1n = tdot_tanh();
            float yn  = pdot_tanh();
            SH0[0][half][j] = h0n;
            SH1[0][half][j] = h1n;
            __syncwarp();
            ldp(h0p, SH0[0][half]);
            ldp(h1p, SH1[0][half]);
            y = yn; yq0 = yn;
        }
        {   // i = 3: h0[3], h1[2], y[1]
            float h0n = sdot_tanh(x03.w);
            float h1n = tdot_tanh();
            float yn  = pdot_tanh();
            SH0[1][half][j] = h0n;
            SH1[1][half][j] = h1n;
            __syncwarp();
            ldp(h0p, SH0[1][half]);
            ldp(h1p, SH1[1][half]);
            y = yn; yq1 = yn;
        }
    }

    // ---- x prefetch: aligned float4, 2-deep ----
    const float4* X = (const float4*)xb;
    float4 xcur = X[1];                       // x[4..7]
    float4 xnxt = X[2];                       // x[8..11]

    // ---- main loop: tc = 4 .. T-4 step 4; iter i = tc+s computes h0[i], h1[i-1], y[i-2] ----
    for (int tc = 4; tc < T; tc += 4) {
#pragma unroll
        for (int s = 0; s < 4; s++) {
            const int slot = s & 1;           // tc is even
            const float xt = (s == 0) ? xcur.x : (s == 1) ? xcur.y : (s == 2) ? xcur.z : xcur.w;

            // All three stage dots read only OLD state -> mutually independent.
            float h0n = sdot_tanh(xt);        // -> h0[i]
            SH0[slot][half][j] = h0n;         // store as soon as available
            float h1n = tdot_tanh();          // -> h1[i-1]
            SH1[slot][half][j] = h1n;
            float yn  = pdot_tanh();          // -> y[i-2]  (issues while STS drains)

            // no barrier: same-address RAW enforced by LSU; 2 slots keep
            // the WAR at distance 2.
            ldp(h0p, SH0[slot][half]);
            ldp(h1p, SH1[slot][half]);
            y = yn;

            // y[i-2] lands at queue position (s+2)&3
            if (s == 0) yq2 = yn;
            else if (s == 1) {
                yq3 = yn;
                if (j == 0) *(float4*)(ob + tc - 4) = make_float4(yq0, yq1, yq2, yq3);
            }
            else if (s == 2) yq0 = yn;
            else yq1 = yn;
        }
        xcur = xnxt;
        xnxt = (tc + 8 < T) ? X[tc / 4 + 2] : xnxt;
    }

    // ---- epilogue: i = T (h1[T-1], y[T-2]), i = T+1 (y[T-1]) ----
    {
        float h1n = tdot_tanh();   // h1[T-1]  (h0p=h0[T-1], h1p=h1[T-2])
        float yn  = pdot_tanh();   // y[T-2]
        SH1[0][half][j] = h1n;
        __syncwarp();
        ldp(h1p, SH1[0][half]);
        y = yn; yq2 = yn;
    }
    {
        float yn = pdot_tanh();    // y[T-1]
        yq3 = yn;
        if (j == 0) *(float4*)(ob + T - 4) = make_float4(yq0, yq1, yq2, yq3);
    }
}

extern "C" void kernel_launch(void* const* d_in, const int* in_sizes, int n_in,
                              void* d_out, int out_size)
{
    const float* x       = (const float*)d_in[0];
    const float* prev_h0 = (const float*)d_in[1];
    const float* post_h0 = (const float*)d_in[2];
    const float* W_ih0   = (const float*)d_in[3];
    const float* W_hh0   = (const float*)d_in[4];
    const float* b_ih0   = (const float*)d_in[5];
    const float* b_hh0   = (const float*)d_in[6];
    const float* W_ih1   = (const float*)d_in[7];
    const float* W_hh1   = (const float*)d_in[8];
    const float* b_ih1   = (const float*)d_in[9];
    const float* b_hh1   = (const float*)d_in[10];
    const float* W_ihp   = (const float*)d_in[11];
    const float* W_hhp   = (const float*)d_in[12];
    const float* b_ihp   = (const float*)d_in[13];
    const float* b_hhp   = (const float*)d_in[14];
    float* out = (float*)d_out;

    const int T = in_sizes[0] / BATCH;   // IN == 1, T = 16384 (multiple of 4)

    rnn3_scan_kernel<<<BATCH / 2, 32>>>(
        x, prev_h0, post_h0,
        W_ih0, W_hh0, b_ih0, b_hh0,
        W_ih1, W_hh1, b_ih1, b_hh1,
        W_ihp, W_hhp, b_ihp, b_hhp,
        out, T);
}